// round 4
// baseline (speedup 1.0000x reference)
#include <cuda_runtime.h>

#define BB 256     // batch
#define TT 256     // time steps
#define DD 64      // input dim
#define HH 512     // hidden
#define OO 10      // output classes

#define NBLK 128   // persistent grid for recurrence (all co-resident, 1/SM)
#define GRP  16    // CTAs per bt dependency group

// ---------------- scratch (static device globals; no allocation allowed) ----
__device__ float g_xp0[TT * BB * HH];     // [t][b][h]
__device__ float g_seq0[TT * BB * HH];    // [t][b][h]
__device__ float g_xp1[TT * BB * HH];     // [t][b][h]
__device__ float g_part[2][2][BB * HH];   // ping-pong x split x [b][j]
__device__ float g_hlast[BB * HH];

__device__ unsigned g_gcnt[8];            // per-bt arrival counters
__device__ unsigned g_ggen[8];            // per-bt generation (monotonic)

// ---------------- packed fp32x2 helpers -------------------------------------
__device__ __forceinline__ unsigned long long dup2(float a) {
    unsigned long long d;
    asm("mov.b64 %0, {%1, %1};" : "=l"(d) : "f"(a));
    return d;
}
__device__ __forceinline__ void fma2(unsigned long long& d,
                                     unsigned long long a, unsigned long long b) {
    asm("fma.rn.f32x2 %0, %1, %2, %0;" : "+l"(d) : "l"(a), "l"(b));
}
__device__ __forceinline__ void unpack2(unsigned long long d, float& lo, float& hi) {
    asm("mov.b64 {%0, %1}, %2;" : "=f"(lo), "=f"(hi) : "l"(d));
}

// ---------------- per-group sense barrier (16 CTAs sharing bt) --------------
__device__ __forceinline__ void grp_bar(int bt) {
    __syncthreads();
    if (threadIdx.x == 0) {
        __threadfence();   // release: partial writes visible before arrival
        unsigned snap = *(volatile unsigned*)&g_ggen[bt];
        unsigned old = atomicAdd(&g_gcnt[bt], 1u);
        if (old == GRP - 1u) {
            g_gcnt[bt] = 0u;
            __threadfence();
            atomicExch(&g_ggen[bt], snap + 1u);
        } else {
            while (*(volatile unsigned*)&g_ggen[bt] == snap) {}
            __threadfence();  // acquire
        }
    }
    __syncthreads();
}

// ---------------- GEMM: C[m][n] = sum_k A[m][k]*W[n][k] + b1[n] + b2[n] -----
// Tile 128m x 64n, BK=16, 256 threads, 4m x 8n micro (fp32x2), double-buffered.
// A smem stored transposed [k][m] (conflict-free vector loads).
__global__ __launch_bounds__(256, 2) void gemm_nt_bias(
    const float* __restrict__ A, const float* __restrict__ Wm,
    const float* __restrict__ b1, const float* __restrict__ b2,
    float* __restrict__ Cm, int M, int N, int K, int permute)
{
    __shared__ float sA[2][16 * 128];   // [k][m]
    __shared__ float sW[2][16 * 64];    // [k][n]

    int m0 = blockIdx.x * 128;
    int n0 = blockIdx.y * 64;
    int tid = threadIdx.x;

    // staging indices
    int srow = tid >> 2;          // 0..63
    int akq  = tid & 3;           // k-quad 0..3

    const float* Ap[2];
#pragma unroll
    for (int it = 0; it < 2; ++it) {
        int gm = m0 + srow + it * 64;
        if (permute) {
            int b_ = gm & (BB - 1);
            int t_ = gm >> 8;                  // BB == 256
            Ap[it] = A + ((size_t)b_ * TT + t_) * K;
        } else {
            Ap[it] = A + (size_t)gm * K;
        }
    }
    const float* Wp = Wm + (size_t)(n0 + srow) * K;

    // compute indices: micro 4m x 8n
    int tn = tid & 7;             // n-oct 0..7  -> n = tn*8
    int tm = tid >> 3;            // 0..31       -> m = tm*4

    unsigned long long acc[4][4];
#pragma unroll
    for (int i = 0; i < 4; ++i)
#pragma unroll
        for (int j = 0; j < 4; ++j) acc[i][j] = 0ull;

    // prologue: stage kt=0 into buffer 0
    float4 a4[2], w4;
#pragma unroll
    for (int it = 0; it < 2; ++it) a4[it] = *(const float4*)(Ap[it] + akq * 4);
    w4 = *(const float4*)(Wp + akq * 4);
    {
        float av[2][4] = {{a4[0].x, a4[0].y, a4[0].z, a4[0].w},
                          {a4[1].x, a4[1].y, a4[1].z, a4[1].w}};
        float wv[4] = {w4.x, w4.y, w4.z, w4.w};
#pragma unroll
        for (int l = 0; l < 4; ++l) {
            sA[0][(akq * 4 + l) * 128 + srow]      = av[0][l];
            sA[0][(akq * 4 + l) * 128 + srow + 64] = av[1][l];
            sW[0][(akq * 4 + l) * 64 + srow]       = wv[l];
        }
    }
    __syncthreads();

    int cur = 0;
    for (int kt = 16; kt < K; kt += 16) {
        // prefetch next chunk (gmem latency overlapped by compute below)
#pragma unroll
        for (int it = 0; it < 2; ++it)
            a4[it] = *(const float4*)(Ap[it] + kt + akq * 4);
        w4 = *(const float4*)(Wp + kt + akq * 4);

        // compute current buffer
#pragma unroll
        for (int kb = 0; kb < 4; ++kb) {
#pragma unroll
            for (int kk = 0; kk < 4; ++kk) {
                int k = kb * 4 + kk;
                float4 av = *(const float4*)&sA[cur][k * 128 + tm * 4];
                ulonglong2 wa = *(const ulonglong2*)&sW[cur][k * 64 + tn * 8];
                ulonglong2 wb = *(const ulonglong2*)&sW[cur][k * 64 + tn * 8 + 4];
                float am[4] = {av.x, av.y, av.z, av.w};
#pragma unroll
                for (int i = 0; i < 4; ++i) {
                    unsigned long long ad = dup2(am[i]);
                    fma2(acc[i][0], ad, wa.x);
                    fma2(acc[i][1], ad, wa.y);
                    fma2(acc[i][2], ad, wb.x);
                    fma2(acc[i][3], ad, wb.y);
                }
            }
        }

        // store prefetched into other buffer
        int nxt = cur ^ 1;
        {
            float av[2][4] = {{a4[0].x, a4[0].y, a4[0].z, a4[0].w},
                              {a4[1].x, a4[1].y, a4[1].z, a4[1].w}};
            float wv[4] = {w4.x, w4.y, w4.z, w4.w};
#pragma unroll
            for (int l = 0; l < 4; ++l) {
                sA[nxt][(akq * 4 + l) * 128 + srow]      = av[0][l];
                sA[nxt][(akq * 4 + l) * 128 + srow + 64] = av[1][l];
                sW[nxt][(akq * 4 + l) * 64 + srow]       = wv[l];
            }
        }
        __syncthreads();
        cur = nxt;
    }
    // last chunk
#pragma unroll
    for (int kb = 0; kb < 4; ++kb) {
#pragma unroll
        for (int kk = 0; kk < 4; ++kk) {
            int k = kb * 4 + kk;
            float4 av = *(const float4*)&sA[cur][k * 128 + tm * 4];
            ulonglong2 wa = *(const ulonglong2*)&sW[cur][k * 64 + tn * 8];
            ulonglong2 wb = *(const ulonglong2*)&sW[cur][k * 64 + tn * 8 + 4];
            float am[4] = {av.x, av.y, av.z, av.w};
#pragma unroll
            for (int i = 0; i < 4; ++i) {
                unsigned long long ad = dup2(am[i]);
                fma2(acc[i][0], ad, wa.x);
                fma2(acc[i][1], ad, wa.y);
                fma2(acc[i][2], ad, wb.x);
                fma2(acc[i][3], ad, wb.y);
            }
        }
    }

    // epilogue: bias + store
    float bias[8];
#pragma unroll
    for (int j = 0; j < 8; ++j) {
        int n = n0 + tn * 8 + j;
        bias[j] = b1[n] + (b2 ? b2[n] : 0.f);
    }
#pragma unroll
    for (int i = 0; i < 4; ++i) {
        float o[8];
        unpack2(acc[i][0], o[0], o[1]);
        unpack2(acc[i][1], o[2], o[3]);
        unpack2(acc[i][2], o[4], o[5]);
        unpack2(acc[i][3], o[6], o[7]);
        float4 lo, hi;
        lo.x = o[0] + bias[0]; lo.y = o[1] + bias[1];
        lo.z = o[2] + bias[2]; lo.w = o[3] + bias[3];
        hi.x = o[4] + bias[4]; hi.y = o[5] + bias[5];
        hi.z = o[6] + bias[6]; hi.w = o[7] + bias[7];
        size_t off = (size_t)(m0 + tm * 4 + i) * N + n0 + tn * 8;
        *(float4*)(Cm + off)     = lo;
        *(float4*)(Cm + off + 4) = hi;
    }
}

// ---------------- persistent recurrence kernel ------------------------------
// h_t = relu(xp[t] + h_{t-1} @ Whh^T), split-K=2, combine-on-load next step.
// CTA (bt, jt, s): 32 b-rows x 64 j-cols, k-half s. 256 threads, 2b x 4j micro
// on the fp32x2 pipe. Whh slice (64j x 256k) persists in SMEM for all steps.
// Synchronization is per-bt group (16 CTAs) — the only true dependency scope.
__global__ __launch_bounds__(256, 1) void rec_kernel(
    const float* __restrict__ xp,      // [T][B][H]
    const float* __restrict__ Whh,     // [H][H]
    float* __restrict__ seq_out,       // [T][B][H] or nullptr
    float* __restrict__ h_last)        // [B][H]    or nullptr
{
    extern __shared__ float smem[];
    float* sW = smem;                  // [256 k][64 j]
    float* sH = smem + 256 * 64;       // [32 b][64 k-chunk]

    int cid = blockIdx.x;
    int s  = cid & 1;
    int jt = (cid >> 1) & 7;
    int bt = cid >> 4;
    int b0 = bt * 32, j0 = jt * 64, k0 = s * 256;
    int gidx = cid & (GRP - 1);        // rank within bt group

    int tid = threadIdx.x;
    int tj = tid & 15;                 // 0..15 -> j = tj*4
    int tb = tid >> 4;                 // 0..15 -> b = tb*2

    // Load Whh slice transposed into sW[k][j] (one time).
    for (int i = tid; i < 64 * 64; i += 256) {
        int kq = i & 63;               // coalesced along k
        int j  = i >> 6;
        float4 w4 = *(const float4*)(Whh + (size_t)(j0 + j) * HH + k0 + kq * 4);
        sW[(kq * 4 + 0) * 64 + j] = w4.x;
        sW[(kq * 4 + 1) * 64 + j] = w4.y;
        sW[(kq * 4 + 2) * 64 + j] = w4.z;
        sW[(kq * 4 + 3) * 64 + j] = w4.w;
    }

    // Zero ping buffer 0 for this group's rows (both splits).
    {
        float4 z = make_float4(0.f, 0.f, 0.f, 0.f);
        // group covers 2 (s) x 32 (b) x 512 (j) floats = 8192 float4
#pragma unroll
        for (int it = 0; it < 2; ++it) {
            int q = gidx * 256 + tid + it * 4096;
            int sp = q >> 12;
            int r  = q & 4095;
            int b  = r >> 7;
            int jq = r & 127;
            *(float4*)&g_part[0][sp][(size_t)(b0 + b) * HH + jq * 4] = z;
        }
    }
    grp_bar(bt);

    const int wr_seq = (seq_out != nullptr) && (jt == 0);

    for (int t = 1; t < TT; ++t) {
        const float* xprev = xp + (size_t)(t - 1) * BB * HH;
        const float* p0 = &g_part[(t - 1) & 1][0][0];
        const float* p1 = &g_part[(t - 1) & 1][1][0];
        float* pw = &g_part[t & 1][s][0];

        unsigned long long acc[2][2];
#pragma unroll
        for (int i = 0; i < 2; ++i) { acc[i][0] = 0ull; acc[i][1] = 0ull; }

        // Prefetch chunk 0 stage data into registers.
        float4 rx[2], rp0[2], rp1[2];
#pragma unroll
        for (int it = 0; it < 2; ++it) {
            int q = tid + it * 256;
            int b = q >> 4, kq = q & 15;
            size_t off = (size_t)(b0 + b) * HH + k0 + kq * 4;
            rx[it]  = *(const float4*)(xprev + off);
            rp0[it] = *(const float4*)(p0 + off);
            rp1[it] = *(const float4*)(p1 + off);
        }

        for (int c = 0; c < 4; ++c) {
            // Combine + store stage (chunk c) to SMEM; optionally emit seq.
#pragma unroll
            for (int it = 0; it < 2; ++it) {
                int q = tid + it * 256;
                int b = q >> 4, kq = q & 15;
                float4 v;
                v.x = fmaxf(rx[it].x + rp0[it].x + rp1[it].x, 0.f);
                v.y = fmaxf(rx[it].y + rp0[it].y + rp1[it].y, 0.f);
                v.z = fmaxf(rx[it].z + rp0[it].z + rp1[it].z, 0.f);
                v.w = fmaxf(rx[it].w + rp0[it].w + rp1[it].w, 0.f);
                *(float4*)&sH[b * 64 + kq * 4] = v;
                if (wr_seq) {
                    size_t off = (size_t)(t - 1) * BB * HH +
                                 (size_t)(b0 + b) * HH + k0 + c * 64 + kq * 4;
                    *(float4*)(seq_out + off) = v;
                }
            }
            __syncthreads();

            // Prefetch next chunk while computing this one.
            if (c < 3) {
#pragma unroll
                for (int it = 0; it < 2; ++it) {
                    int q = tid + it * 256;
                    int b = q >> 4, kq = q & 15;
                    size_t off = (size_t)(b0 + b) * HH + k0 + (c + 1) * 64 + kq * 4;
                    rx[it]  = *(const float4*)(xprev + off);
                    rp0[it] = *(const float4*)(p0 + off);
                    rp1[it] = *(const float4*)(p1 + off);
                }
            }

            // Compute: 64 k per chunk, 2b x 4j micro on fp32x2.
#pragma unroll
            for (int kq2 = 0; kq2 < 16; ++kq2) {
                float4 av0 = *(const float4*)&sH[(tb * 2 + 0) * 64 + kq2 * 4];
                float4 av1 = *(const float4*)&sH[(tb * 2 + 1) * 64 + kq2 * 4];
                ulonglong2 wv[4];
#pragma unroll
                for (int kk = 0; kk < 4; ++kk)
                    wv[kk] = *(const ulonglong2*)
                             &sW[(c * 64 + kq2 * 4 + kk) * 64 + tj * 4];
                float a0[4] = {av0.x, av0.y, av0.z, av0.w};
                float a1[4] = {av1.x, av1.y, av1.z, av1.w};
#pragma unroll
                for (int kk = 0; kk < 4; ++kk) {
                    unsigned long long d0 = dup2(a0[kk]);
                    unsigned long long d1 = dup2(a1[kk]);
                    fma2(acc[0][0], d0, wv[kk].x);
                    fma2(acc[0][1], d0, wv[kk].y);
                    fma2(acc[1][0], d1, wv[kk].x);
                    fma2(acc[1][1], d1, wv[kk].y);
                }
            }
            __syncthreads();
        }

        // Write split partials for h_t.
#pragma unroll
        for (int i = 0; i < 2; ++i) {
            float4 o;
            unpack2(acc[i][0], o.x, o.y);
            unpack2(acc[i][1], o.z, o.w);
            *(float4*)(pw + (size_t)(b0 + tb * 2 + i) * HH + j0 + tj * 4) = o;
        }
        grp_bar(bt);
    }

    // Final combine for h_{T-1}: jt==0 CTAs (one per k-half per group).
    if (jt == 0) {
        const float* xl = xp + (size_t)(TT - 1) * BB * HH;
        const float* p0 = &g_part[(TT - 1) & 1][0][0];
        const float* p1 = &g_part[(TT - 1) & 1][1][0];
        for (int i = tid; i < 32 * 64; i += 256) {   // 32 rows x 64 f4
            int b = i >> 6;
            int kq = i & 63;
            size_t off = (size_t)(b0 + b) * HH + k0 + kq * 4;
            float4 x4 = *(const float4*)(xl + off);
            float4 a4 = *(const float4*)(p0 + off);
            float4 c4 = *(const float4*)(p1 + off);
            float4 v;
            v.x = fmaxf(x4.x + a4.x + c4.x, 0.f);
            v.y = fmaxf(x4.y + a4.y + c4.y, 0.f);
            v.z = fmaxf(x4.z + a4.z + c4.z, 0.f);
            v.w = fmaxf(x4.w + a4.w + c4.w, 0.f);
            if (seq_out)
                *(float4*)(seq_out + (size_t)(TT - 1) * BB * HH + off) = v;
            if (h_last)
                *(float4*)(h_last + off) = v;
        }
    }
}

// ---------------- head: relu(h @ fc1^T + b1) @ fc2^T + b2 -------------------
__global__ __launch_bounds__(256) void head_kernel(
    const float* __restrict__ hl, const float* __restrict__ w1,
    const float* __restrict__ b1f, const float* __restrict__ w2,
    const float* __restrict__ b2f, float* __restrict__ out)
{
    __shared__ float sh[8];
    int b = blockIdx.x;
    int tid = threadIdx.x;
    int w = tid >> 5;
    int lane = tid & 31;

    const float* hb = hl + (size_t)b * HH;
    const float* wr = w1 + (size_t)w * HH;
    float ssum = 0.f;
    for (int k = lane; k < HH; k += 32) ssum += hb[k] * wr[k];
#pragma unroll
    for (int o = 16; o; o >>= 1) ssum += __shfl_xor_sync(0xffffffffu, ssum, o);
    if (lane == 0) sh[w] = fmaxf(ssum + b1f[w], 0.f);
    __syncthreads();
    if (tid < OO) {
        float r = b2f[tid];
#pragma unroll
        for (int j = 0; j < 8; ++j) r += sh[j] * w2[tid * 8 + j];
        out[(size_t)b * OO + tid] = r;
    }
}

// ---------------- launch ----------------------------------------------------
extern "C" void kernel_launch(void* const* d_in, const int* in_sizes, int n_in,
                              void* d_out, int out_size)
{
    const float* x     = (const float*)d_in[0];
    const float* w_ih0 = (const float*)d_in[1];
    const float* w_hh0 = (const float*)d_in[2];
    const float* b_ih0 = (const float*)d_in[3];
    const float* b_hh0 = (const float*)d_in[4];
    const float* w_ih1 = (const float*)d_in[5];
    const float* w_hh1 = (const float*)d_in[6];
    const float* b_ih1 = (const float*)d_in[7];
    const float* b_hh1 = (const float*)d_in[8];
    const float* fc1_w = (const float*)d_in[9];
    const float* fc1_b = (const float*)d_in[10];
    const float* fc2_w = (const float*)d_in[11];
    const float* fc2_b = (const float*)d_in[12];
    float* out = (float*)d_out;

    void* p;
    cudaGetSymbolAddress(&p, g_xp0);   float* xp0   = (float*)p;
    cudaGetSymbolAddress(&p, g_seq0);  float* seq0  = (float*)p;
    cudaGetSymbolAddress(&p, g_xp1);   float* xp1   = (float*)p;
    cudaGetSymbolAddress(&p, g_hlast); float* hlast = (float*)p;

    size_t rec_smem = (size_t)(256 * 64 + 32 * 64) * sizeof(float);  // 73728 B
    cudaFuncSetAttribute(rec_kernel,
                         cudaFuncAttributeMaxDynamicSharedMemorySize,
                         (int)rec_smem);

    dim3 gg(TT * BB / 128, HH / 64);   // 512 x 8

    // layer-0 input projection (rows permuted from x[b][t][d])
    gemm_nt_bias<<<gg, 256>>>(x, w_ih0, b_ih0, b_hh0, xp0,
                              TT * BB, HH, DD, 1);
    // layer-0 recurrence (writes seq0)
    rec_kernel<<<NBLK, 256, rec_smem>>>(xp0, w_hh0, seq0, nullptr);
    // layer-1 input projection
    gemm_nt_bias<<<gg, 256>>>(seq0, w_ih1, b_ih1, b_hh1, xp1,
                              TT * BB, HH, HH, 0);
    // layer-1 recurrence (only final hidden state needed)
    rec_kernel<<<NBLK, 256, rec_smem>>>(xp1, w_hh1, nullptr, hlast);
    // head
    head_kernel<<<BB, 256>>>(hlast, fc1_w, fc1_b, fc2_w, fc2_b, out);
}

// round 5
// speedup vs baseline: 1.0972x; 1.0972x over previous
#include <cuda_runtime.h>

#define BB 256     // batch
#define TT 256     // time steps
#define DD 64      // input dim
#define HH 512     // hidden
#define OO 10      // output classes

#define NBLK 128   // rec grid: 4 bt x 2 jt x 16 sk (all co-resident, 1/SM)
#define GRP  32    // CTAs per bt dependency group
#define NSK  16    // K-splits in recurrence

// ---------------- scratch (static device globals; no allocation allowed) ----
__device__ float g_xp0[TT * BB * HH];        // [t][b][h]
__device__ float g_seq0[TT * BB * HH];       // [t][b][h]
__device__ float g_xp1[TT * BB * HH];        // [t][b][h]
__device__ float g_part[2][NSK][BB * HH];    // ping-pong x split x [b][j]
__device__ float g_hlast[BB * HH];

__device__ unsigned g_gcnt[4];               // per-bt arrival counters
__device__ unsigned g_ggen[4];               // per-bt generation

// ---------------- packed fp32x2 helpers -------------------------------------
__device__ __forceinline__ unsigned long long dup2(float a) {
    unsigned long long d;
    asm("mov.b64 %0, {%1, %1};" : "=l"(d) : "f"(a));
    return d;
}
__device__ __forceinline__ void fma2(unsigned long long& d,
                                     unsigned long long a, unsigned long long b) {
    asm("fma.rn.f32x2 %0, %1, %2, %0;" : "+l"(d) : "l"(a), "l"(b));
}
__device__ __forceinline__ void unpack2(unsigned long long d, float& lo, float& hi) {
    asm("mov.b64 {%0, %1}, %2;" : "=f"(lo), "=f"(hi) : "l"(d));
}

// ---------------- per-group sense barrier (32 CTAs sharing bt) --------------
__device__ __forceinline__ void grp_bar(int bt) {
    __syncthreads();
    if (threadIdx.x == 0) {
        __threadfence();   // release: partial writes visible before arrival
        unsigned snap = *(volatile unsigned*)&g_ggen[bt];
        unsigned old = atomicAdd(&g_gcnt[bt], 1u);
        if (old == GRP - 1u) {
            g_gcnt[bt] = 0u;
            __threadfence();
            atomicExch(&g_ggen[bt], snap + 1u);
        } else {
            while (*(volatile unsigned*)&g_ggen[bt] == snap) {}
            __threadfence();  // acquire
        }
    }
    __syncthreads();
}

// ---------------- GEMM: C[m][n] = sum_k A[m][k]*W[n][k] + b1[n] + b2[n] -----
// Tile 128m x 128n, BK=16, 256 threads, 8m x 8n micro (fp32x2, 1 B/MAC),
// double-buffered. Both smem tiles stored transposed [k][row].
__global__ __launch_bounds__(256, 2) void gemm_nt_bias(
    const float* __restrict__ A, const float* __restrict__ Wm,
    const float* __restrict__ b1, const float* __restrict__ b2,
    float* __restrict__ Cm, int M, int N, int K, int permute)
{
    __shared__ float sA[2][16 * 128];   // [k][m]
    __shared__ float sW[2][16 * 128];   // [k][n]

    int m0 = blockIdx.x * 128;
    int n0 = blockIdx.y * 128;
    int tid = threadIdx.x;

    // staging: 512 float4 tasks per array, 2 per thread
    int row0 = tid >> 1;          // task tid    : row = tid>>1?? use q-mapping below
    (void)row0;

    // q in {tid, tid+256}: row = q>>2 (0..127), kq = q&3
    const float* Ap[2];
    const float* Wp[2];
#pragma unroll
    for (int it = 0; it < 2; ++it) {
        int q = tid + it * 256;
        int row = q >> 2;
        int gm = m0 + row;
        if (permute) {
            int b_ = gm & (BB - 1);
            int t_ = gm >> 8;                  // BB == 256
            Ap[it] = A + ((size_t)b_ * TT + t_) * K;
        } else {
            Ap[it] = A + (size_t)gm * K;
        }
        Wp[it] = Wm + (size_t)(n0 + row) * K;
    }

    int tn = tid & 15;            // -> n = tn*8
    int tm = tid >> 4;            // -> m = tm*8

    unsigned long long acc[4][8]; // [m-pair][n]
#pragma unroll
    for (int i = 0; i < 4; ++i)
#pragma unroll
        for (int j = 0; j < 8; ++j) acc[i][j] = 0ull;

    // prologue: stage chunk 0
    float4 a4[2], w4[2];
#pragma unroll
    for (int it = 0; it < 2; ++it) {
        int q = tid + it * 256;
        int kq = q & 3;
        a4[it] = *(const float4*)(Ap[it] + kq * 4);
        w4[it] = *(const float4*)(Wp[it] + kq * 4);
    }
#pragma unroll
    for (int it = 0; it < 2; ++it) {
        int q = tid + it * 256;
        int row = q >> 2, kq = q & 3;
        float av[4] = {a4[it].x, a4[it].y, a4[it].z, a4[it].w};
        float wv[4] = {w4[it].x, w4[it].y, w4[it].z, w4[it].w};
#pragma unroll
        for (int l = 0; l < 4; ++l) {
            sA[0][(kq * 4 + l) * 128 + row] = av[l];
            sW[0][(kq * 4 + l) * 128 + row] = wv[l];
        }
    }
    __syncthreads();

    int cur = 0;
    for (int kt = 16; kt < K; kt += 16) {
        // prefetch next chunk
#pragma unroll
        for (int it = 0; it < 2; ++it) {
            int q = tid + it * 256;
            int kq = q & 3;
            a4[it] = *(const float4*)(Ap[it] + kt + kq * 4);
            w4[it] = *(const float4*)(Wp[it] + kt + kq * 4);
        }
        // compute current chunk
#pragma unroll
        for (int k = 0; k < 16; ++k) {
            ulonglong2 m01 = *(const ulonglong2*)&sA[cur][k * 128 + tm * 8];
            ulonglong2 m23 = *(const ulonglong2*)&sA[cur][k * 128 + tm * 8 + 4];
            float4 wA = *(const float4*)&sW[cur][k * 128 + tn * 8];
            float4 wB = *(const float4*)&sW[cur][k * 128 + tn * 8 + 4];
            unsigned long long wd[8];
            wd[0] = dup2(wA.x); wd[1] = dup2(wA.y);
            wd[2] = dup2(wA.z); wd[3] = dup2(wA.w);
            wd[4] = dup2(wB.x); wd[5] = dup2(wB.y);
            wd[6] = dup2(wB.z); wd[7] = dup2(wB.w);
            unsigned long long hp[4] = {m01.x, m01.y, m23.x, m23.y};
#pragma unroll
            for (int i = 0; i < 4; ++i)
#pragma unroll
                for (int j = 0; j < 8; ++j)
                    fma2(acc[i][j], hp[i], wd[j]);
        }
        // store prefetched
        int nxt = cur ^ 1;
#pragma unroll
        for (int it = 0; it < 2; ++it) {
            int q = tid + it * 256;
            int row = q >> 2, kq = q & 3;
            float av[4] = {a4[it].x, a4[it].y, a4[it].z, a4[it].w};
            float wv[4] = {w4[it].x, w4[it].y, w4[it].z, w4[it].w};
#pragma unroll
            for (int l = 0; l < 4; ++l) {
                sA[nxt][(kq * 4 + l) * 128 + row] = av[l];
                sW[nxt][(kq * 4 + l) * 128 + row] = wv[l];
            }
        }
        __syncthreads();
        cur = nxt;
    }
    // last chunk
#pragma unroll
    for (int k = 0; k < 16; ++k) {
        ulonglong2 m01 = *(const ulonglong2*)&sA[cur][k * 128 + tm * 8];
        ulonglong2 m23 = *(const ulonglong2*)&sA[cur][k * 128 + tm * 8 + 4];
        float4 wA = *(const float4*)&sW[cur][k * 128 + tn * 8];
        float4 wB = *(const float4*)&sW[cur][k * 128 + tn * 8 + 4];
        unsigned long long wd[8];
        wd[0] = dup2(wA.x); wd[1] = dup2(wA.y);
        wd[2] = dup2(wA.z); wd[3] = dup2(wA.w);
        wd[4] = dup2(wB.x); wd[5] = dup2(wB.y);
        wd[6] = dup2(wB.z); wd[7] = dup2(wB.w);
        unsigned long long hp[4] = {m01.x, m01.y, m23.x, m23.y};
#pragma unroll
        for (int i = 0; i < 4; ++i)
#pragma unroll
            for (int j = 0; j < 8; ++j)
                fma2(acc[i][j], hp[i], wd[j]);
    }

    // epilogue
    float bias[8];
#pragma unroll
    for (int j = 0; j < 8; ++j) {
        int n = n0 + tn * 8 + j;
        bias[j] = b1[n] + (b2 ? b2[n] : 0.f);
    }
#pragma unroll
    for (int i = 0; i < 4; ++i) {
        float r0[8], r1[8];
#pragma unroll
        for (int j = 0; j < 8; ++j) unpack2(acc[i][j], r0[j], r1[j]);
        int m = m0 + tm * 8 + i * 2;
        size_t off0 = (size_t)m * N + n0 + tn * 8;
        size_t off1 = off0 + N;
        float4 v;
        v.x = r0[0] + bias[0]; v.y = r0[1] + bias[1];
        v.z = r0[2] + bias[2]; v.w = r0[3] + bias[3];
        *(float4*)(Cm + off0) = v;
        v.x = r0[4] + bias[4]; v.y = r0[5] + bias[5];
        v.z = r0[6] + bias[6]; v.w = r0[7] + bias[7];
        *(float4*)(Cm + off0 + 4) = v;
        v.x = r1[0] + bias[0]; v.y = r1[1] + bias[1];
        v.z = r1[2] + bias[2]; v.w = r1[3] + bias[3];
        *(float4*)(Cm + off1) = v;
        v.x = r1[4] + bias[4]; v.y = r1[5] + bias[5];
        v.z = r1[6] + bias[6]; v.w = r1[7] + bias[7];
        *(float4*)(Cm + off1 + 4) = v;
    }
}

// ---------------- persistent recurrence kernel ------------------------------
// h_t = relu(xp[t-1] + h_{t-1} @ Whh^T).
// Grid 128 = 4 bt x 2 jt x 16 sk. CTA tile: 64b x 256j, K-slice of 32.
// Consumer-side combine: each CTA rebuilds its own A-slice h[64b, k0..k0+32]
// by summing the 16 K-split partials (+xp, relu) directly into SMEM.
// 256 threads, micro 8b x 8j on fp32x2 (1 B/MAC -> LDS == FMA floor).
// Whh slice (256j x 32k) persists in SMEM transposed.
__global__ __launch_bounds__(256, 1) void rec_kernel(
    const float* __restrict__ xp,      // [T][B][H]
    const float* __restrict__ Whh,     // [H][H]
    float* __restrict__ seq_out,       // [T][B][H] or nullptr
    float* __restrict__ h_last)        // [B][H]    or nullptr
{
    extern __shared__ float smem[];
    float* sW = smem;                  // [32 k][256 j]  32 KB
    float* sA = smem + 32 * 256;       // [32 k][64 b]    8 KB

    int cid = blockIdx.x;
    int bt = cid >> 5;                 // 0..3
    int jt = (cid >> 4) & 1;           // 0..1
    int sk = cid & 15;                 // 0..15
    int b0 = bt * 64, j0 = jt * 256, k0 = sk * 32;

    int tid = threadIdx.x;

    // Load Whh slice transposed: sW[k][j] = Whh[j0+j][k0+k]
    for (int i = tid; i < 2048; i += 256) {
        int j  = i >> 3;               // 0..255
        int kq = i & 7;                // 0..7
        float4 w4 = *(const float4*)(Whh + (size_t)(j0 + j) * HH + k0 + kq * 4);
        sW[(kq * 4 + 0) * 256 + j] = w4.x;
        sW[(kq * 4 + 1) * 256 + j] = w4.y;
        sW[(kq * 4 + 2) * 256 + j] = w4.z;
        sW[(kq * 4 + 3) * 256 + j] = w4.w;
    }

    // Zero own region of ping buffer 0: p[0][sk][b0..b0+64][j0..j0+256]
    for (int i = tid; i < 4096; i += 256) {   // 64 rows x 64 float4
        int b  = i >> 6;
        int jq = i & 63;
        *(float4*)&g_part[0][sk][(size_t)(b0 + b) * HH + j0 + jq * 4] =
            make_float4(0.f, 0.f, 0.f, 0.f);
    }
    grp_bar(bt);

    const int wr_seq = (seq_out != nullptr) && (jt == 0);

    // combine indices: thread -> (b = tid>>2, jj = (tid&3)*8)
    int cb  = tid >> 2;
    int cj  = (tid & 3) * 8;
    // micro indices: 8 tb-groups x 32 tj-groups
    int tb = tid >> 5;                 // -> b = tb*8
    int tj = tid & 31;                 // -> j = tj*8

    for (int t = 1; t < TT; ++t) {
        const float* pbase = &g_part[(t - 1) & 1][0][0];
        const float* xprev = xp + (size_t)(t - 1) * BB * HH;
        float* pw = &g_part[t & 1][sk][0];

        // ---- combine: h[b0+cb][k0+cj..+8] = relu(xp + sum_s p[s]) -> sA ----
        {
            size_t rowoff = (size_t)(b0 + cb) * HH + k0 + cj;
            float4 s0 = *(const float4*)(xprev + rowoff);
            float4 s1 = *(const float4*)(xprev + rowoff + 4);
#pragma unroll
            for (int s2 = 0; s2 < NSK; ++s2) {
                const float* ps = pbase + (size_t)s2 * (BB * HH) + rowoff;
                float4 q0 = *(const float4*)(ps);
                float4 q1 = *(const float4*)(ps + 4);
                s0.x += q0.x; s0.y += q0.y; s0.z += q0.z; s0.w += q0.w;
                s1.x += q1.x; s1.y += q1.y; s1.z += q1.z; s1.w += q1.w;
            }
            s0.x = fmaxf(s0.x, 0.f); s0.y = fmaxf(s0.y, 0.f);
            s0.z = fmaxf(s0.z, 0.f); s0.w = fmaxf(s0.w, 0.f);
            s1.x = fmaxf(s1.x, 0.f); s1.y = fmaxf(s1.y, 0.f);
            s1.z = fmaxf(s1.z, 0.f); s1.w = fmaxf(s1.w, 0.f);
            // transposed store: sA[jj][b]
            sA[(cj + 0) * 64 + cb] = s0.x;
            sA[(cj + 1) * 64 + cb] = s0.y;
            sA[(cj + 2) * 64 + cb] = s0.z;
            sA[(cj + 3) * 64 + cb] = s0.w;
            sA[(cj + 4) * 64 + cb] = s1.x;
            sA[(cj + 5) * 64 + cb] = s1.y;
            sA[(cj + 6) * 64 + cb] = s1.z;
            sA[(cj + 7) * 64 + cb] = s1.w;
            if (wr_seq) {
                float* so = seq_out + (size_t)(t - 1) * BB * HH + rowoff;
                *(float4*)(so)     = s0;
                *(float4*)(so + 4) = s1;
            }
        }
        __syncthreads();

        // ---- MMA: acc[b 8][j 8] += sum_{k=0..31} h[k][b] * W[k][j] --------
        unsigned long long acc[4][8];
#pragma unroll
        for (int i = 0; i < 4; ++i)
#pragma unroll
            for (int j = 0; j < 8; ++j) acc[i][j] = 0ull;

#pragma unroll
        for (int k = 0; k < 32; ++k) {
            ulonglong2 h01 = *(const ulonglong2*)&sA[k * 64 + tb * 8];
            ulonglong2 h23 = *(const ulonglong2*)&sA[k * 64 + tb * 8 + 4];
            float4 wA = *(const float4*)&sW[k * 256 + tj * 8];
            float4 wB = *(const float4*)&sW[k * 256 + tj * 8 + 4];
            unsigned long long wd[8];
            wd[0] = dup2(wA.x); wd[1] = dup2(wA.y);
            wd[2] = dup2(wA.z); wd[3] = dup2(wA.w);
            wd[4] = dup2(wB.x); wd[5] = dup2(wB.y);
            wd[6] = dup2(wB.z); wd[7] = dup2(wB.w);
            unsigned long long hp[4] = {h01.x, h01.y, h23.x, h23.y};
#pragma unroll
            for (int i = 0; i < 4; ++i)
#pragma unroll
                for (int j = 0; j < 8; ++j)
                    fma2(acc[i][j], hp[i], wd[j]);
        }

        // ---- write partials: rows b0+tb*8+bp*2(+1), cols j0+tj*8..+8 ------
#pragma unroll
        for (int i = 0; i < 4; ++i) {
            float r0[8], r1[8];
#pragma unroll
            for (int j = 0; j < 8; ++j) unpack2(acc[i][j], r0[j], r1[j]);
            size_t off0 = (size_t)(b0 + tb * 8 + i * 2) * HH + j0 + tj * 8;
            size_t off1 = off0 + HH;
            float4 v;
            v.x = r0[0]; v.y = r0[1]; v.z = r0[2]; v.w = r0[3];
            *(float4*)(pw + off0) = v;
            v.x = r0[4]; v.y = r0[5]; v.z = r0[6]; v.w = r0[7];
            *(float4*)(pw + off0 + 4) = v;
            v.x = r1[0]; v.y = r1[1]; v.z = r1[2]; v.w = r1[3];
            *(float4*)(pw + off1) = v;
            v.x = r1[4]; v.y = r1[5]; v.z = r1[6]; v.w = r1[7];
            *(float4*)(pw + off1 + 4) = v;
        }
        grp_bar(bt);
    }

    // ---- final combine: h_T slice written by jt==0 CTAs --------------------
    if (jt == 0) {
        const float* pbase = &g_part[(TT - 1) & 1][0][0];
        const float* xl = xp + (size_t)(TT - 1) * BB * HH;
        size_t rowoff = (size_t)(b0 + cb) * HH + k0 + cj;
        float4 s0 = *(const float4*)(xl + rowoff);
        float4 s1 = *(const float4*)(xl + rowoff + 4);
#pragma unroll
        for (int s2 = 0; s2 < NSK; ++s2) {
            const float* ps = pbase + (size_t)s2 * (BB * HH) + rowoff;
            float4 q0 = *(const float4*)(ps);
            float4 q1 = *(const float4*)(ps + 4);
            s0.x += q0.x; s0.y += q0.y; s0.z += q0.z; s0.w += q0.w;
            s1.x += q1.x; s1.y += q1.y; s1.z += q1.z; s1.w += q1.w;
        }
        s0.x = fmaxf(s0.x, 0.f); s0.y = fmaxf(s0.y, 0.f);
        s0.z = fmaxf(s0.z, 0.f); s0.w = fmaxf(s0.w, 0.f);
        s1.x = fmaxf(s1.x, 0.f); s1.y = fmaxf(s1.y, 0.f);
        s1.z = fmaxf(s1.z, 0.f); s1.w = fmaxf(s1.w, 0.f);
        if (seq_out) {
            float* so = seq_out + (size_t)(TT - 1) * BB * HH + rowoff;
            *(float4*)(so)     = s0;
            *(float4*)(so + 4) = s1;
        }
        if (h_last) {
            *(float4*)(h_last + rowoff)     = s0;
            *(float4*)(h_last + rowoff + 4) = s1;
        }
    }
}

// ---------------- head: relu(h @ fc1^T + b1) @ fc2^T + b2 -------------------
__global__ __launch_bounds__(256) void head_kernel(
    const float* __restrict__ hl, const float* __restrict__ w1,
    const float* __restrict__ b1f, const float* __restrict__ w2,
    const float* __restrict__ b2f, float* __restrict__ out)
{
    __shared__ float sh[8];
    int b = blockIdx.x;
    int tid = threadIdx.x;
    int w = tid >> 5;
    int lane = tid & 31;

    const float* hb = hl + (size_t)b * HH;
    const float* wr = w1 + (size_t)w * HH;
    float ssum = 0.f;
    for (int k = lane; k < HH; k += 32) ssum += hb[k] * wr[k];
#pragma unroll
    for (int o = 16; o; o >>= 1) ssum += __shfl_xor_sync(0xffffffffu, ssum, o);
    if (lane == 0) sh[w] = fmaxf(ssum + b1f[w], 0.f);
    __syncthreads();
    if (tid < OO) {
        float r = b2f[tid];
#pragma unroll
        for (int j = 0; j < 8; ++j) r += sh[j] * w2[tid * 8 + j];
        out[(size_t)b * OO + tid] = r;
    }
}

// ---------------- launch ----------------------------------------------------
extern "C" void kernel_launch(void* const* d_in, const int* in_sizes, int n_in,
                              void* d_out, int out_size)
{
    const float* x     = (const float*)d_in[0];
    const float* w_ih0 = (const float*)d_in[1];
    const float* w_hh0 = (const float*)d_in[2];
    const float* b_ih0 = (const float*)d_in[3];
    const float* b_hh0 = (const float*)d_in[4];
    const float* w_ih1 = (const float*)d_in[5];
    const float* w_hh1 = (const float*)d_in[6];
    const float* b_ih1 = (const float*)d_in[7];
    const float* b_hh1 = (const float*)d_in[8];
    const float* fc1_w = (const float*)d_in[9];
    const float* fc1_b = (const float*)d_in[10];
    const float* fc2_w = (const float*)d_in[11];
    const float* fc2_b = (const float*)d_in[12];
    float* out = (float*)d_out;

    void* p;
    cudaGetSymbolAddress(&p, g_xp0);   float* xp0   = (float*)p;
    cudaGetSymbolAddress(&p, g_seq0);  float* seq0  = (float*)p;
    cudaGetSymbolAddress(&p, g_xp1);   float* xp1   = (float*)p;
    cudaGetSymbolAddress(&p, g_hlast); float* hlast = (float*)p;

    size_t rec_smem = (size_t)(32 * 256 + 32 * 64) * sizeof(float);  // 40960 B
    cudaFuncSetAttribute(rec_kernel,
                         cudaFuncAttributeMaxDynamicSharedMemorySize,
                         (int)rec_smem);

    dim3 gg(TT * BB / 128, HH / 128);   // 512 x 4

    // layer-0 input projection (rows permuted from x[b][t][d])
    gemm_nt_bias<<<gg, 256>>>(x, w_ih0, b_ih0, b_hh0, xp0,
                              TT * BB, HH, DD, 1);
    // layer-0 recurrence (writes seq0)
    rec_kernel<<<NBLK, 256, rec_smem>>>(xp0, w_hh0, seq0, nullptr);
    // layer-1 input projection
    gemm_nt_bias<<<gg, 256>>>(seq0, w_ih1, b_ih1, b_hh1, xp1,
                              TT * BB, HH, HH, 0);
    // layer-1 recurrence (only final hidden state needed)
    rec_kernel<<<NBLK, 256, rec_smem>>>(xp1, w_hh1, nullptr, hlast);
    // head
    head_kernel<<<BB, 256>>>(hlast, fc1_w, fc1_b, fc2_w, fc2_b, out);
}